// round 13
// baseline (speedup 1.0000x reference)
#include <cuda_runtime.h>
#include <math.h>

// ---------------------------------------------------------------------------
// Projection_12438225290005: tube-of-response projection, 3 axis frames.
//
// R12 = R11 with the ring taps rewritten for forced PREDICATION.
// Hot-kernel ncu (pz, 217us): issue=89.3% binding, L1=79.4%, alu=50.5% —
// ~1090 issued inst/warp-LOR vs ~530 static = ptxas compiled the 12
// `else if (d2<KW2) {5-inst body}` ring taps as BSSY/BRA/BSYNC branch blocks.
// Fix: single-instruction conditional body (`if (pass) v = __ldg(...)`),
// unconditional w (MUFU already issued), fmaf(w, v, t) with v=0 for inactive
// taps (exact: w finite for d2>=0.5, w*0=0). Target: issue ~660/warp-LOR,
// pz -> ~180us at the L1 wavefront floor (L1% should rise toward 90+).
//
// Carried invariants (verified): cross taps unconditional (d2<=2.5<9/pi),
// corners pruned (d2>=4.5), sqrt=d2*rsqrt(d2), parity accumulators, prep
// folds per-LOR setup, g_imgT device-side, launch_bounds(256,6),
// launch order keeps pz at slot #4 for ncu.
// ---------------------------------------------------------------------------

#define G 128
#define GSQ (G * G)
#define MAX_LORS (1 << 20)
#define WARPS_PER_BLOCK 8

__device__ float  g_imgT[G * G * G];          // transposed image for px frame
__device__ float4 g_prm[3][MAX_LORS];         // Ax, Bx, Ay, By
__device__ float  g_stp[3][MAX_LORS];         // step

// g_imgT[a][c][b] = in[a][b][c]
__global__ void transpose_bc_kernel(const float* __restrict__ in) {
    __shared__ float tile[32][33];
    const int a  = blockIdx.z;
    const int b0 = blockIdx.y * 32;
    const int c0 = blockIdx.x * 32;
    const float* src = in     + (size_t)a * GSQ;
    float*       dst = g_imgT + (size_t)a * GSQ;
#pragma unroll
    for (int i = threadIdx.y; i < 32; i += 8)
        tile[i][threadIdx.x] = src[(b0 + i) * G + c0 + threadIdx.x];
    __syncthreads();
#pragma unroll
    for (int i = threadIdx.y; i < 32; i += 8)
        dst[(c0 + i) * G + b0 + threadIdx.x] = tile[threadIdx.x][i];
}

// One thread per LOR. P0/P1/P2 permute grid/center/size ONLY (lors are
// already frame-local — verified by passing rounds).
template <int P0, int P1, int P2>
__global__ void prep_kernel(const int*   __restrict__ grid,
                            const float* __restrict__ center,
                            const float* __restrict__ size,
                            const float* __restrict__ lors,
                            int n, int set)
{
    int i = blockIdx.x * blockDim.x + threadIdx.x;
    if (i >= n) return;
    const float sz0 = size[P0], sz1 = size[P1], sz2 = size[P2];
    const int   n0 = grid[P0], n1 = grid[P1], n2 = grid[P2];
    const float vs0 = sz0 / (float)n0;
    const float vs1 = sz1 / (float)n1;
    const float vs2 = sz2 / (float)n2;
    const float lo0 = center[P0] - 0.5f * sz0;
    const float lo1 = center[P1] - 0.5f * sz1;
    const float lo2 = center[P2] - 0.5f * sz2;

    const float* L = lors + (size_t)i * 6;
    const float p10 = L[0], p11 = L[1], p12 = L[2];
    const float d0  = L[3] - p10;
    const float d1  = L[4] - p11;
    const float d2c = L[5] - p12;
    const float len = sqrtf(d0 * d0 + d1 * d1 + d2c * d2c);
    const float inv_dz = 1.0f / d2c;
    const float t0 = (lo2 + 0.5f * vs2 - p12) * inv_dz;   // t(kz)=t0+kz*dt
    const float dt = vs2 * inv_dz;
    const float Ax = (p10 + t0 * d0 - lo0) / vs0 - 0.5f;
    const float Bx = dt * d0 / vs0;
    const float Ay = (p11 + t0 * d1 - lo1) / vs1 - 0.5f;
    const float By = dt * d1 / vs1;
    g_prm[set][i] = make_float4(Ax, Bx, Ay, By);
    g_stp[set][i] = vs2 * len / fabsf(d2c);
}

// sqrt(d2) via one MUFU.RSQ + FMUL. Guarded variant only for d2 that can be 0.
__device__ __forceinline__ float fast_sqrt_guard(float d2) {
    return d2 * rsqrtf(fmaxf(d2, 1e-30f));
}
__device__ __forceinline__ float fast_sqrt_nz(float d2) {   // d2 >= 0.25
    return d2 * rsqrtf(d2);
}

// Hot kernel: one WARP per LOR; lane handles kz = lane + 32j, j=0..3.
template <int S0, int S1, bool TPOSE>
__global__ __launch_bounds__(32 * WARPS_PER_BLOCK, 6)
void tor_fast_kernel(const float* __restrict__ img_in, int set,
                     float* __restrict__ out, int n_lors)
{
    const float* img = TPOSE ? (const float*)g_imgT : img_in;

    const int warp = threadIdx.x >> 5;
    const int lane = threadIdx.x & 31;
    const int lor  = blockIdx.x * WARPS_PER_BLOCK + warp;
    if (lor >= n_lors) return;

    const float4 P = __ldg(&g_prm[set][lor]);

    const float KW2    = 2.8647889756541160f;   // 9/pi
    const float INV_KW = 0.59081795026046127f;  // 1/sqrt(9/pi)

    float accE = 0.0f, accO = 0.0f;   // parity-split accumulators

#pragma unroll
    for (int j = 0; j < 4; ++j) {
        const int   kz  = lane + 32 * j;
        const float kzf = (float)kz;
        const float fx = fmaf(kzf, P.y, P.x);
        const float fy = fmaf(kzf, P.w, P.z);
        const int ix = __float2int_rn(fx);   // half-to-even == jnp.round
        const int iy = __float2int_rn(fy);

        const float ux = (float)ix - fx;     // in [-0.5, 0.5]
        const float uy = (float)iy - fy;
        float xs[5], ys[5];
#pragma unroll
        for (int o = 0; o < 5; ++o) {
            const float a = ux + (float)(o - 2);
            const float b = uy + (float)(o - 2);
            xs[o] = a * a;
            ys[o] = b * b;
        }

        float t0 = 0.0f, t1 = 0.0f;        // per-group temporaries (2 chains)

        if ((unsigned)(ix - 2) <= (unsigned)(G - 5) &&
            (unsigned)(iy - 2) <= (unsigned)(G - 5)) {
            const float* p = img + ix * S0 + iy * S1 + kz;
#pragma unroll
            for (int o0 = -2; o0 <= 2; ++o0) {
#pragma unroll
                for (int o1 = -2; o1 <= 2; ++o1) {
                    const int r2 = o0 * o0 + o1 * o1;
                    if (r2 == 8) continue;               // corners: never pass
                    const float d2 = xs[o0 + 2] + ys[o1 + 2];
                    const bool even = (((o0 + o1) & 1) == 0);
                    if (r2 == 0) {
                        // center tap: always pass, d2 may be 0 -> guarded sqrt
                        const float w = fmaf(-fast_sqrt_guard(d2), INV_KW, 1.0f);
                        t0 = fmaf(w, __ldg(p), t0);
                    } else if (r2 <= 1) {
                        // other cross taps: always pass, d2 >= 0.25
                        const float w = fmaf(-fast_sqrt_nz(d2), INV_KW, 1.0f);
                        const float v = __ldg(p + (o0 * S0 + o1 * S1));
                        if (even) t0 = fmaf(w, v, t0); else t1 = fmaf(w, v, t1);
                    } else {
                        // ring taps: PREDICATED single-inst conditional load.
                        // w computed unconditionally (finite: d2>=0.5);
                        // inactive taps add w*0 = 0 exactly.
                        const float w = fmaf(-fast_sqrt_nz(d2), INV_KW, 1.0f);
                        float v = 0.0f;
                        if (d2 < KW2) v = __ldg(p + (o0 * S0 + o1 * S1));
                        if (even) t0 = fmaf(w, v, t0); else t1 = fmaf(w, v, t1);
                    }
                }
            }
        } else {
            // edge fallback (not hit for this dataset): per-tap bounds
#pragma unroll
            for (int o0 = -2; o0 <= 2; ++o0) {
#pragma unroll
                for (int o1 = -2; o1 <= 2; ++o1) {
                    if (o0 * o0 + o1 * o1 == 8) continue;
                    const int jx = ix + o0;
                    const int jy = iy + o1;
                    const float d2 = xs[o0 + 2] + ys[o1 + 2];
                    if (d2 < KW2 && (unsigned)jx < (unsigned)G && (unsigned)jy < (unsigned)G) {
                        const float w = fmaf(-fast_sqrt_guard(d2), INV_KW, 1.0f);
                        t0 = fmaf(w, __ldg(img + jx * S0 + jy * S1 + kz), t0);
                    }
                }
            }
        }

        accE += t0;
        accO += t1;
    }

    float acc = accE + accO;

    // warp reduction
#pragma unroll
    for (int sft = 16; sft > 0; sft >>= 1)
        acc += __shfl_down_sync(0xFFFFFFFFu, acc, sft);
    if (lane == 0)
        out[lor] = acc * __ldg(&g_stp[set][lor]);
}

// ------------------------ generic fallback -----------------------------------
template <int P0, int P1, int P2>
__global__ __launch_bounds__(128)
void tor_generic_kernel(const float* __restrict__ img_in,
                        const int*   __restrict__ grid,
                        const float* __restrict__ center,
                        const float* __restrict__ size,
                        const float* __restrict__ lors,
                        float*       __restrict__ out,
                        int n_lors)
{
    const int lor = blockIdx.x;
    if (lor >= n_lors) return;
    const int g0 = grid[0], g1 = grid[1], g2 = grid[2];
    const int gs[3]   = { g0, g1, g2 };
    const int istr[3] = { g1 * g2, g2, 1 };
    const int n0 = gs[P0], n1 = gs[P1], n2 = gs[P2];
    const int s0 = istr[P0], s1 = istr[P1], s2 = istr[P2];
    const float* img = img_in;

    const float sz0 = size[P0], sz1 = size[P1], sz2 = size[P2];
    const float vs0 = sz0 / (float)n0, vs1 = sz1 / (float)n1, vs2 = sz2 / (float)n2;
    const float lo0 = center[P0] - sz0 * 0.5f;
    const float lo1 = center[P1] - sz1 * 0.5f;
    const float lo2 = center[P2] - sz2 * 0.5f;

    const float* L = lors + (size_t)lor * 6;
    const float p1x = __ldg(L + 0), p1y = __ldg(L + 1), p1z = __ldg(L + 2);
    const float dx = __ldg(L + 3) - p1x, dy = __ldg(L + 4) - p1y, dz = __ldg(L + 5) - p1z;
    const float len = sqrtf(dx * dx + dy * dy + dz * dz);
    const float step = vs2 * len / fabsf(dz);
    const float inv_dz = 1.0f / dz, inv_vs0 = 1.0f / vs0, inv_vs1 = 1.0f / vs1;
    const float KW2 = 2.8647889756541160f, INV_KW = 0.59081795026046127f;

    float acc = 0.0f;
    for (int kz = threadIdx.x; kz < n2; kz += blockDim.x) {
        const float zc = lo2 + ((float)kz + 0.5f) * vs2;
        const float t  = (zc - p1z) * inv_dz;
        const float fx = (fmaf(t, dx, p1x) - lo0) * inv_vs0 - 0.5f;
        const float fy = (fmaf(t, dy, p1y) - lo1) * inv_vs1 - 0.5f;
        const int ix = __float2int_rn(fx);
        const int iy = __float2int_rn(fy);
#pragma unroll
        for (int o0 = -2; o0 <= 2; ++o0) {
#pragma unroll
            for (int o1 = -2; o1 <= 2; ++o1) {
                if (o0 * o0 + o1 * o1 == 8) continue;
                const int jx = ix + o0, jy = iy + o1;
                const float ddx = (float)jx - fx, ddy = (float)jy - fy;
                const float d2 = ddx * ddx + ddy * ddy;
                if (d2 < KW2 && (unsigned)jx < (unsigned)n0 && (unsigned)jy < (unsigned)n1) {
                    const float s = d2 * rsqrtf(fmaxf(d2, 1e-30f));
                    const float w = fmaf(-s, INV_KW, 1.0f);
                    acc = fmaf(w, __ldg(&img[jx * s0 + jy * s1 + kz * s2]), acc);
                }
            }
        }
    }
#pragma unroll
    for (int sft = 16; sft > 0; sft >>= 1)
        acc += __shfl_down_sync(0xFFFFFFFFu, acc, sft);
    __shared__ float wsum[4];
    if ((threadIdx.x & 31) == 0) wsum[threadIdx.x >> 5] = acc;
    __syncthreads();
    if (threadIdx.x == 0)
        out[lor] = (wsum[0] + wsum[1] + wsum[2] + wsum[3]) * step;
}

extern "C" void kernel_launch(void* const* d_in, const int* in_sizes, int n_in,
                              void* d_out, int out_size)
{
    const float* image  = (const float*)d_in[0];
    const int*   grid   = (const int*)  d_in[1];
    const float* center = (const float*)d_in[2];
    const float* size   = (const float*)d_in[3];
    const float* xlors  = (const float*)d_in[4];
    const float* ylors  = (const float*)d_in[5];
    const float* zlors  = (const float*)d_in[6];
    float* out = (float*)d_out;

    const int nx = in_sizes[4] / 6;
    const int ny = in_sizes[5] / 6;
    const int nz = in_sizes[6] / 6;

    const long long nimg = in_sizes[0];
    const bool fast = (nimg == (long long)G * G * G) &&
                      nx <= MAX_LORS && ny <= MAX_LORS && nz <= MAX_LORS;

    if (fast) {
        const int PT = 256;
        const int W = WARPS_PER_BLOCK;

        // Launch order: ncu capture lands on launch #4 -> hot pz kernel.
        if (nz > 0) prep_kernel<0, 1, 2><<<(nz + PT - 1) / PT, PT>>>(grid, center, size, zlors, nz, 2);
        if (nx > 0) prep_kernel<2, 0, 1><<<(nx + PT - 1) / PT, PT>>>(grid, center, size, xlors, nx, 0);
        if (ny > 0) prep_kernel<1, 0, 2><<<(ny + PT - 1) / PT, PT>>>(grid, center, size, ylors, ny, 1);

        // #4: pz hot kernel (image[jx][jy][kz] -> S0=GSQ, S1=G) — PROFILED
        if (nz > 0) tor_fast_kernel<GSQ, G,   false><<<(nz + W - 1) / W, 32 * W>>>(image, 2, out + nx + ny, nz);

        // #5: transpose for px frame (walked image axis must be stride-1)
        {
            dim3 tb(32, 8), tg(G / 32, G / 32, G);
            transpose_bc_kernel<<<tg, tb>>>(image);
        }

        // #6: px (g_imgT[jy][jx][kz] -> S0=G, S1=GSQ, TPOSE)
        if (nx > 0) tor_fast_kernel<G,   GSQ, true ><<<(nx + W - 1) / W, 32 * W>>>(image, 0, out, nx);
        // #7: py (image[jy][jx][kz] -> S0=G, S1=GSQ)
        if (ny > 0) tor_fast_kernel<G,   GSQ, false><<<(ny + W - 1) / W, 32 * W>>>(image, 1, out + nx, ny);
    } else {
        if (nx > 0) tor_generic_kernel<2, 0, 1><<<nx, 128>>>(image, grid, center, size, xlors, out, nx);
        if (ny > 0) tor_generic_kernel<1, 0, 2><<<ny, 128>>>(image, grid, center, size, ylors, out + nx, ny);
        if (nz > 0) tor_generic_kernel<0, 1, 2><<<nz, 128>>>(image, grid, center, size, zlors, out + nx + ny, nz);
    }
}

// round 14
// speedup vs baseline: 1.0423x; 1.0423x over previous
#include <cuda_runtime.h>
#include <math.h>

// ---------------------------------------------------------------------------
// Projection_12438225290005: tube-of-response projection, 3 axis frames.
//
// R13 = R12 + issue-count trim toward the L1 wall (pz ncu: issue 88%,
// fma 50%, alu 45%, L1 81% — issue port binding, L1 ~10% behind):
//   1. xs/ys squared-offset tables computed in packed f32x2 (PTX-only
//      add.rn.f32x2 / mul.rn.f32x2): 20 scalar ops/group -> 11.
//   2. interior bounds test hoisted to whole-LOR (fx,fy linear in kz ->
//      endpoint test, conservative [2.0,125.0]); edge LORs use exact path.
//   3. launch_bounds(256,5) so extra regs don't spill.
// Tap math otherwise identical to R12 (rel_err 1.4e-7 verified).
// ---------------------------------------------------------------------------

#define G 128
#define GSQ (G * G)
#define MAX_LORS (1 << 20)
#define WARPS_PER_BLOCK 8

__device__ float  g_imgT[G * G * G];          // transposed image for px frame
__device__ float4 g_prm[3][MAX_LORS];         // Ax, Bx, Ay, By
__device__ float  g_stp[3][MAX_LORS];         // step

// ---- f32x2 packed helpers (sm_103a; ptxas emits these only via PTX) -------
__device__ __forceinline__ unsigned long long f2x_pack(float lo, float hi) {
    unsigned long long r;
    asm("mov.b64 %0, {%1, %2};" : "=l"(r) : "f"(lo), "f"(hi));
    return r;
}
__device__ __forceinline__ unsigned long long f2x_add(unsigned long long a,
                                                      unsigned long long b) {
    unsigned long long r;
    asm("add.rn.f32x2 %0, %1, %2;" : "=l"(r) : "l"(a), "l"(b));
    return r;
}
__device__ __forceinline__ unsigned long long f2x_mul(unsigned long long a,
                                                      unsigned long long b) {
    unsigned long long r;
    asm("mul.rn.f32x2 %0, %1, %2;" : "=l"(r) : "l"(a), "l"(b));
    return r;
}
__device__ __forceinline__ void f2x_unpack(unsigned long long v,
                                           float& lo, float& hi) {
    asm("mov.b64 {%0, %1}, %2;" : "=f"(lo), "=f"(hi) : "l"(v));
}

// g_imgT[a][c][b] = in[a][b][c]
__global__ void transpose_bc_kernel(const float* __restrict__ in) {
    __shared__ float tile[32][33];
    const int a  = blockIdx.z;
    const int b0 = blockIdx.y * 32;
    const int c0 = blockIdx.x * 32;
    const float* src = in     + (size_t)a * GSQ;
    float*       dst = g_imgT + (size_t)a * GSQ;
#pragma unroll
    for (int i = threadIdx.y; i < 32; i += 8)
        tile[i][threadIdx.x] = src[(b0 + i) * G + c0 + threadIdx.x];
    __syncthreads();
#pragma unroll
    for (int i = threadIdx.y; i < 32; i += 8)
        dst[(c0 + i) * G + b0 + threadIdx.x] = tile[threadIdx.x][i];
}

// One thread per LOR. P0/P1/P2 permute grid/center/size ONLY (lors are
// already frame-local — verified by passing rounds).
template <int P0, int P1, int P2>
__global__ void prep_kernel(const int*   __restrict__ grid,
                            const float* __restrict__ center,
                            const float* __restrict__ size,
                            const float* __restrict__ lors,
                            int n, int set)
{
    int i = blockIdx.x * blockDim.x + threadIdx.x;
    if (i >= n) return;
    const float sz0 = size[P0], sz1 = size[P1], sz2 = size[P2];
    const int   n0 = grid[P0], n1 = grid[P1], n2 = grid[P2];
    const float vs0 = sz0 / (float)n0;
    const float vs1 = sz1 / (float)n1;
    const float vs2 = sz2 / (float)n2;
    const float lo0 = center[P0] - 0.5f * sz0;
    const float lo1 = center[P1] - 0.5f * sz1;
    const float lo2 = center[P2] - 0.5f * sz2;

    const float* L = lors + (size_t)i * 6;
    const float p10 = L[0], p11 = L[1], p12 = L[2];
    const float d0  = L[3] - p10;
    const float d1  = L[4] - p11;
    const float d2c = L[5] - p12;
    const float len = sqrtf(d0 * d0 + d1 * d1 + d2c * d2c);
    const float inv_dz = 1.0f / d2c;
    const float t0 = (lo2 + 0.5f * vs2 - p12) * inv_dz;   // t(kz)=t0+kz*dt
    const float dt = vs2 * inv_dz;
    const float Ax = (p10 + t0 * d0 - lo0) / vs0 - 0.5f;
    const float Bx = dt * d0 / vs0;
    const float Ay = (p11 + t0 * d1 - lo1) / vs1 - 0.5f;
    const float By = dt * d1 / vs1;
    g_prm[set][i] = make_float4(Ax, Bx, Ay, By);
    g_stp[set][i] = vs2 * len / fabsf(d2c);
}

// sqrt(d2) via one MUFU.RSQ + FMUL. Guarded variant only for d2 that can be 0.
__device__ __forceinline__ float fast_sqrt_guard(float d2) {
    return d2 * rsqrtf(fmaxf(d2, 1e-30f));
}
__device__ __forceinline__ float fast_sqrt_nz(float d2) {   // d2 >= 0.25
    return d2 * rsqrtf(d2);
}

// Hot kernel: one WARP per LOR; lane handles kz = lane + 32j, j=0..3.
template <int S0, int S1, bool TPOSE>
__global__ __launch_bounds__(32 * WARPS_PER_BLOCK, 5)
void tor_fast_kernel(const float* __restrict__ img_in, int set,
                     float* __restrict__ out, int n_lors)
{
    const float* img = TPOSE ? (const float*)g_imgT : img_in;

    const int warp = threadIdx.x >> 5;
    const int lane = threadIdx.x & 31;
    const int lor  = blockIdx.x * WARPS_PER_BLOCK + warp;
    if (lor >= n_lors) return;

    const float4 P = __ldg(&g_prm[set][lor]);

    const float KW2    = 2.8647889756541160f;   // 9/pi
    const float INV_KW = 0.59081795026046127f;  // 1/sqrt(9/pi)

    // Whole-LOR interior test: fx,fy linear in kz -> check both endpoints
    // (kz=lane and kz=lane+96). Conservative float bounds [2.0,125.0] give
    // ix,iy in [2,125] -> all 5x5 taps in [0,127]. Edge LORs -> exact path.
    const float fxa = fmaf((float)lane, P.y, P.x);
    const float fya = fmaf((float)lane, P.w, P.z);
    const float fxb = fmaf(96.0f, P.y, fxa);
    const float fyb = fmaf(96.0f, P.w, fya);
    const bool interior =
        fminf(fminf(fxa, fxb), fminf(fya, fyb)) >= 2.0f &&
        fmaxf(fmaxf(fxa, fxb), fmaxf(fya, fyb)) <= 125.0f;

    // packed constants for the xs/ys chain
    const unsigned long long MTWO2 = f2x_pack(-2.0f, -2.0f);
    const unsigned long long ONE2  = f2x_pack( 1.0f,  1.0f);

    float accE = 0.0f, accO = 0.0f;   // parity-split accumulators

    if (interior) {
#pragma unroll
        for (int j = 0; j < 4; ++j) {
            const int   kz  = lane + 32 * j;
            const float fx = (j == 0) ? fxa : fmaf((float)(32 * j), P.y, fxa);
            const float fy = (j == 0) ? fya : fmaf((float)(32 * j), P.w, fya);
            const int ix = __float2int_rn(fx);   // half-to-even == jnp.round
            const int iy = __float2int_rn(fy);

            const float ux = (float)ix - fx;     // in [-0.5, 0.5]
            const float uy = (float)iy - fy;

            // packed (ux+o, uy+o)^2 chain: 1 pack + 5 ADD2 + 5 MUL2
            float xs[5], ys[5];
            {
                unsigned long long A = f2x_add(f2x_pack(ux, uy), MTWO2);
                unsigned long long S = f2x_mul(A, A);
                f2x_unpack(S, xs[0], ys[0]);
#pragma unroll
                for (int o = 1; o < 5; ++o) {
                    A = f2x_add(A, ONE2);
                    S = f2x_mul(A, A);
                    f2x_unpack(S, xs[o], ys[o]);
                }
            }

            float t0 = 0.0f, t1 = 0.0f;
            const float* p = img + ix * S0 + iy * S1 + kz;
#pragma unroll
            for (int o0 = -2; o0 <= 2; ++o0) {
#pragma unroll
                for (int o1 = -2; o1 <= 2; ++o1) {
                    const int r2 = o0 * o0 + o1 * o1;
                    if (r2 == 8) continue;               // corners: never pass
                    const float d2 = xs[o0 + 2] + ys[o1 + 2];
                    const bool even = (((o0 + o1) & 1) == 0);
                    if (r2 == 0) {
                        const float w = fmaf(-fast_sqrt_guard(d2), INV_KW, 1.0f);
                        t0 = fmaf(w, __ldg(p), t0);
                    } else if (r2 <= 1) {
                        const float w = fmaf(-fast_sqrt_nz(d2), INV_KW, 1.0f);
                        const float v = __ldg(p + (o0 * S0 + o1 * S1));
                        if (even) t0 = fmaf(w, v, t0); else t1 = fmaf(w, v, t1);
                    } else {
                        // ring: predicated 2-inst conditional body
                        const float w = fmaf(-fast_sqrt_nz(d2), INV_KW, 1.0f);
                        if (d2 < KW2) {
                            const float v = __ldg(p + (o0 * S0 + o1 * S1));
                            if (even) t0 = fmaf(w, v, t0); else t1 = fmaf(w, v, t1);
                        }
                    }
                }
            }
            accE += t0;
            accO += t1;
        }
    } else {
        // edge LORs (not hit for this dataset): exact per-tap bounds
#pragma unroll
        for (int j = 0; j < 4; ++j) {
            const int   kz  = lane + 32 * j;
            const float kzf = (float)kz;
            const float fx = fmaf(kzf, P.y, P.x);
            const float fy = fmaf(kzf, P.w, P.z);
            const int ix = __float2int_rn(fx);
            const int iy = __float2int_rn(fy);
            const float ux = (float)ix - fx;
            const float uy = (float)iy - fy;
            float t0 = 0.0f;
#pragma unroll
            for (int o0 = -2; o0 <= 2; ++o0) {
#pragma unroll
                for (int o1 = -2; o1 <= 2; ++o1) {
                    if (o0 * o0 + o1 * o1 == 8) continue;
                    const int jx = ix + o0;
                    const int jy = iy + o1;
                    const float ddx = ux + (float)o0;
                    const float ddy = uy + (float)o1;
                    const float d2 = ddx * ddx + ddy * ddy;
                    if (d2 < KW2 && (unsigned)jx < (unsigned)G && (unsigned)jy < (unsigned)G) {
                        const float w = fmaf(-fast_sqrt_guard(d2), INV_KW, 1.0f);
                        t0 = fmaf(w, __ldg(img + jx * S0 + jy * S1 + kz), t0);
                    }
                }
            }
            accE += t0;
        }
    }

    float acc = accE + accO;

    // warp reduction
#pragma unroll
    for (int sft = 16; sft > 0; sft >>= 1)
        acc += __shfl_down_sync(0xFFFFFFFFu, acc, sft);
    if (lane == 0)
        out[lor] = acc * __ldg(&g_stp[set][lor]);
}

// ------------------------ generic fallback -----------------------------------
template <int P0, int P1, int P2>
__global__ __launch_bounds__(128)
void tor_generic_kernel(const float* __restrict__ img_in,
                        const int*   __restrict__ grid,
                        const float* __restrict__ center,
                        const float* __restrict__ size,
                        const float* __restrict__ lors,
                        float*       __restrict__ out,
                        int n_lors)
{
    const int lor = blockIdx.x;
    if (lor >= n_lors) return;
    const int g0 = grid[0], g1 = grid[1], g2 = grid[2];
    const int gs[3]   = { g0, g1, g2 };
    const int istr[3] = { g1 * g2, g2, 1 };
    const int n0 = gs[P0], n1 = gs[P1], n2 = gs[P2];
    const int s0 = istr[P0], s1 = istr[P1], s2 = istr[P2];
    const float* img = img_in;

    const float sz0 = size[P0], sz1 = size[P1], sz2 = size[P2];
    const float vs0 = sz0 / (float)n0, vs1 = sz1 / (float)n1, vs2 = sz2 / (float)n2;
    const float lo0 = center[P0] - sz0 * 0.5f;
    const float lo1 = center[P1] - sz1 * 0.5f;
    const float lo2 = center[P2] - sz2 * 0.5f;

    const float* L = lors + (size_t)lor * 6;
    const float p1x = __ldg(L + 0), p1y = __ldg(L + 1), p1z = __ldg(L + 2);
    const float dx = __ldg(L + 3) - p1x, dy = __ldg(L + 4) - p1y, dz = __ldg(L + 5) - p1z;
    const float len = sqrtf(dx * dx + dy * dy + dz * dz);
    const float step = vs2 * len / fabsf(dz);
    const float inv_dz = 1.0f / dz, inv_vs0 = 1.0f / vs0, inv_vs1 = 1.0f / vs1;
    const float KW2 = 2.8647889756541160f, INV_KW = 0.59081795026046127f;

    float acc = 0.0f;
    for (int kz = threadIdx.x; kz < n2; kz += blockDim.x) {
        const float zc = lo2 + ((float)kz + 0.5f) * vs2;
        const float t  = (zc - p1z) * inv_dz;
        const float fx = (fmaf(t, dx, p1x) - lo0) * inv_vs0 - 0.5f;
        const float fy = (fmaf(t, dy, p1y) - lo1) * inv_vs1 - 0.5f;
        const int ix = __float2int_rn(fx);
        const int iy = __float2int_rn(fy);
#pragma unroll
        for (int o0 = -2; o0 <= 2; ++o0) {
#pragma unroll
            for (int o1 = -2; o1 <= 2; ++o1) {
                if (o0 * o0 + o1 * o1 == 8) continue;
                const int jx = ix + o0, jy = iy + o1;
                const float ddx = (float)jx - fx, ddy = (float)jy - fy;
                const float d2 = ddx * ddx + ddy * ddy;
                if (d2 < KW2 && (unsigned)jx < (unsigned)n0 && (unsigned)jy < (unsigned)n1) {
                    const float s = d2 * rsqrtf(fmaxf(d2, 1e-30f));
                    const float w = fmaf(-s, INV_KW, 1.0f);
                    acc = fmaf(w, __ldg(&img[jx * s0 + jy * s1 + kz * s2]), acc);
                }
            }
        }
    }
#pragma unroll
    for (int sft = 16; sft > 0; sft >>= 1)
        acc += __shfl_down_sync(0xFFFFFFFFu, acc, sft);
    __shared__ float wsum[4];
    if ((threadIdx.x & 31) == 0) wsum[threadIdx.x >> 5] = acc;
    __syncthreads();
    if (threadIdx.x == 0)
        out[lor] = (wsum[0] + wsum[1] + wsum[2] + wsum[3]) * step;
}

extern "C" void kernel_launch(void* const* d_in, const int* in_sizes, int n_in,
                              void* d_out, int out_size)
{
    const float* image  = (const float*)d_in[0];
    const int*   grid   = (const int*)  d_in[1];
    const float* center = (const float*)d_in[2];
    const float* size   = (const float*)d_in[3];
    const float* xlors  = (const float*)d_in[4];
    const float* ylors  = (const float*)d_in[5];
    const float* zlors  = (const float*)d_in[6];
    float* out = (float*)d_out;

    const int nx = in_sizes[4] / 6;
    const int ny = in_sizes[5] / 6;
    const int nz = in_sizes[6] / 6;

    const long long nimg = in_sizes[0];
    const bool fast = (nimg == (long long)G * G * G) &&
                      nx <= MAX_LORS && ny <= MAX_LORS && nz <= MAX_LORS;

    if (fast) {
        const int PT = 256;
        const int W = WARPS_PER_BLOCK;

        // Launch order: ncu capture lands on launch #4 -> hot pz kernel.
        if (nz > 0) prep_kernel<0, 1, 2><<<(nz + PT - 1) / PT, PT>>>(grid, center, size, zlors, nz, 2);
        if (nx > 0) prep_kernel<2, 0, 1><<<(nx + PT - 1) / PT, PT>>>(grid, center, size, xlors, nx, 0);
        if (ny > 0) prep_kernel<1, 0, 2><<<(ny + PT - 1) / PT, PT>>>(grid, center, size, ylors, ny, 1);

        // #4: pz hot kernel (image[jx][jy][kz] -> S0=GSQ, S1=G) — PROFILED
        if (nz > 0) tor_fast_kernel<GSQ, G,   false><<<(nz + W - 1) / W, 32 * W>>>(image, 2, out + nx + ny, nz);

        // #5: transpose for px frame (walked image axis must be stride-1)
        {
            dim3 tb(32, 8), tg(G / 32, G / 32, G);
            transpose_bc_kernel<<<tg, tb>>>(image);
        }

        // #6: px (g_imgT[jy][jx][kz] -> S0=G, S1=GSQ, TPOSE)
        if (nx > 0) tor_fast_kernel<G,   GSQ, true ><<<(nx + W - 1) / W, 32 * W>>>(image, 0, out, nx);
        // #7: py (image[jy][jx][kz] -> S0=G, S1=GSQ)
        if (ny > 0) tor_fast_kernel<G,   GSQ, false><<<(ny + W - 1) / W, 32 * W>>>(image, 1, out + nx, ny);
    } else {
        if (nx > 0) tor_generic_kernel<2, 0, 1><<<nx, 128>>>(image, grid, center, size, xlors, out, nx);
        if (ny > 0) tor_generic_kernel<1, 0, 2><<<ny, 128>>>(image, grid, center, size, ylors, out + nx, ny);
        if (nz > 0) tor_generic_kernel<0, 1, 2><<<nz, 128>>>(image, grid, center, size, zlors, out + nx + ny, nz);
    }
}

// round 15
// speedup vs baseline: 1.0549x; 1.0121x over previous
#include <cuda_runtime.h>
#include <math.h>

// ---------------------------------------------------------------------------
// Projection_12438225290005: tube-of-response projection, 3 axis frames.
//
// R14 = R13 + kw-prescaling: u' = u/kw, o' = o/kw  =>  d2' = d2/kw^2 and
//   w = 1 - sqrt(d2)/kw = 1 - sqrt(d2') = fmaf(-d2', rsqrt(d2'), 1.0)
// deletes the per-tap FMUL (x17 taps x4 groups = 64 inst/warp-LOR, ~8% of
// issue) and makes the ring test `d2' < 1.0f`. Issue is the proven wall
// (89%; occupancy drop 70->57% was free in R13). Everything else from R13:
// hoisted whole-LOR interior test, packed f32x2 xs/ys chain, warp-per-LOR,
// parity accumulators, conditional ring loads, prep-kernel coefficients,
// g_imgT device-side, launch_bounds(256,5), pz at launch slot #4 for ncu.
// ---------------------------------------------------------------------------

#define G 128
#define GSQ (G * G)
#define MAX_LORS (1 << 20)
#define WARPS_PER_BLOCK 8

__device__ float  g_imgT[G * G * G];          // transposed image for px frame
__device__ float4 g_prm[3][MAX_LORS];         // Ax, Bx, Ay, By
__device__ float  g_stp[3][MAX_LORS];         // step

// ---- f32x2 packed helpers (sm_103a; ptxas emits these only via PTX) -------
__device__ __forceinline__ unsigned long long f2x_pack(float lo, float hi) {
    unsigned long long r;
    asm("mov.b64 %0, {%1, %2};" : "=l"(r) : "f"(lo), "f"(hi));
    return r;
}
__device__ __forceinline__ unsigned long long f2x_add(unsigned long long a,
                                                      unsigned long long b) {
    unsigned long long r;
    asm("add.rn.f32x2 %0, %1, %2;" : "=l"(r) : "l"(a), "l"(b));
    return r;
}
__device__ __forceinline__ unsigned long long f2x_mul(unsigned long long a,
                                                      unsigned long long b) {
    unsigned long long r;
    asm("mul.rn.f32x2 %0, %1, %2;" : "=l"(r) : "l"(a), "l"(b));
    return r;
}
__device__ __forceinline__ void f2x_unpack(unsigned long long v,
                                           float& lo, float& hi) {
    asm("mov.b64 {%0, %1}, %2;" : "=f"(lo), "=f"(hi) : "l"(v));
}

// g_imgT[a][c][b] = in[a][b][c]
__global__ void transpose_bc_kernel(const float* __restrict__ in) {
    __shared__ float tile[32][33];
    const int a  = blockIdx.z;
    const int b0 = blockIdx.y * 32;
    const int c0 = blockIdx.x * 32;
    const float* src = in     + (size_t)a * GSQ;
    float*       dst = g_imgT + (size_t)a * GSQ;
#pragma unroll
    for (int i = threadIdx.y; i < 32; i += 8)
        tile[i][threadIdx.x] = src[(b0 + i) * G + c0 + threadIdx.x];
    __syncthreads();
#pragma unroll
    for (int i = threadIdx.y; i < 32; i += 8)
        dst[(c0 + i) * G + b0 + threadIdx.x] = tile[threadIdx.x][i];
}

// One thread per LOR. P0/P1/P2 permute grid/center/size ONLY (lors are
// already frame-local — verified by passing rounds).
template <int P0, int P1, int P2>
__global__ void prep_kernel(const int*   __restrict__ grid,
                            const float* __restrict__ center,
                            const float* __restrict__ size,
                            const float* __restrict__ lors,
                            int n, int set)
{
    int i = blockIdx.x * blockDim.x + threadIdx.x;
    if (i >= n) return;
    const float sz0 = size[P0], sz1 = size[P1], sz2 = size[P2];
    const int   n0 = grid[P0], n1 = grid[P1], n2 = grid[P2];
    const float vs0 = sz0 / (float)n0;
    const float vs1 = sz1 / (float)n1;
    const float vs2 = sz2 / (float)n2;
    const float lo0 = center[P0] - 0.5f * sz0;
    const float lo1 = center[P1] - 0.5f * sz1;
    const float lo2 = center[P2] - 0.5f * sz2;

    const float* L = lors + (size_t)i * 6;
    const float p10 = L[0], p11 = L[1], p12 = L[2];
    const float d0  = L[3] - p10;
    const float d1  = L[4] - p11;
    const float d2c = L[5] - p12;
    const float len = sqrtf(d0 * d0 + d1 * d1 + d2c * d2c);
    const float inv_dz = 1.0f / d2c;
    const float t0 = (lo2 + 0.5f * vs2 - p12) * inv_dz;   // t(kz)=t0+kz*dt
    const float dt = vs2 * inv_dz;
    const float Ax = (p10 + t0 * d0 - lo0) / vs0 - 0.5f;
    const float Bx = dt * d0 / vs0;
    const float Ay = (p11 + t0 * d1 - lo1) / vs1 - 0.5f;
    const float By = dt * d1 / vs1;
    g_prm[set][i] = make_float4(Ax, Bx, Ay, By);
    g_stp[set][i] = vs2 * len / fabsf(d2c);
}

// Hot kernel: one WARP per LOR; lane handles kz = lane + 32j, j=0..3.
template <int S0, int S1, bool TPOSE>
__global__ __launch_bounds__(32 * WARPS_PER_BLOCK, 5)
void tor_fast_kernel(const float* __restrict__ img_in, int set,
                     float* __restrict__ out, int n_lors)
{
    const float* img = TPOSE ? (const float*)g_imgT : img_in;

    const int warp = threadIdx.x >> 5;
    const int lane = threadIdx.x & 31;
    const int lor  = blockIdx.x * WARPS_PER_BLOCK + warp;
    if (lor >= n_lors) return;

    const float4 P = __ldg(&g_prm[set][lor]);

    const float IK  = 0.59081795026046127f;  // 1/kw = 1/sqrt(9/pi)
    const float KW2 = 2.8647889756541160f;   // 9/pi (edge path, unscaled)

    // Whole-LOR interior test: fx,fy linear in kz -> check both endpoints.
    const float fxa = fmaf((float)lane, P.y, P.x);
    const float fya = fmaf((float)lane, P.w, P.z);
    const float fxb = fmaf(96.0f, P.y, fxa);
    const float fyb = fmaf(96.0f, P.w, fya);
    const bool interior =
        fminf(fminf(fxa, fxb), fminf(fya, fyb)) >= 2.0f &&
        fmaxf(fmaxf(fxa, fxb), fmaxf(fya, fyb)) <= 125.0f;

    // packed constants: scaled offset chain (u + o)/kw
    const unsigned long long IK2   = f2x_pack(IK, IK);
    const unsigned long long M2IK2 = f2x_pack(-2.0f * IK, -2.0f * IK);

    float accE = 0.0f, accO = 0.0f;   // parity-split accumulators

    if (interior) {
#pragma unroll
        for (int j = 0; j < 4; ++j) {
            const int   kz  = lane + 32 * j;
            const float fx = (j == 0) ? fxa : fmaf((float)(32 * j), P.y, fxa);
            const float fy = (j == 0) ? fya : fmaf((float)(32 * j), P.w, fya);
            const int ix = __float2int_rn(fx);   // half-to-even == jnp.round
            const int iy = __float2int_rn(fy);

            const float ux = (float)ix - fx;     // in [-0.5, 0.5]
            const float uy = (float)iy - fy;

            // scaled squared-offset tables: xs[o] = ((ux+o-2)/kw)^2 etc.
            // chain: U' = (ux,uy)*IK; A = U' - 2*IK; A += IK; S = A*A
            float xs[5], ys[5];
            {
                unsigned long long A =
                    f2x_add(f2x_mul(f2x_pack(ux, uy), IK2), M2IK2);
                unsigned long long S = f2x_mul(A, A);
                f2x_unpack(S, xs[0], ys[0]);
#pragma unroll
                for (int o = 1; o < 5; ++o) {
                    A = f2x_add(A, IK2);
                    S = f2x_mul(A, A);
                    f2x_unpack(S, xs[o], ys[o]);
                }
            }

            float t0 = 0.0f, t1 = 0.0f;
            const float* p = img + ix * S0 + iy * S1 + kz;
#pragma unroll
            for (int o0 = -2; o0 <= 2; ++o0) {
#pragma unroll
                for (int o1 = -2; o1 <= 2; ++o1) {
                    const int r2 = o0 * o0 + o1 * o1;
                    if (r2 == 8) continue;               // corners: never pass
                    const float d2 = xs[o0 + 2] + ys[o1 + 2];   // = d2/kw^2
                    const bool even = (((o0 + o1) & 1) == 0);
                    if (r2 == 0) {
                        // center: d2 may be 0 -> guard inside rsqrt;
                        // fmaf(-0, inf, 1) = 1 exact.
                        const float w = fmaf(-d2, rsqrtf(fmaxf(d2, 1e-30f)), 1.0f);
                        t0 = fmaf(w, __ldg(p), t0);
                    } else if (r2 <= 1) {
                        // cross taps: always pass; d2 >= (0.5/kw)^2 > 0
                        const float w = fmaf(-d2, rsqrtf(d2), 1.0f);
                        const float v = __ldg(p + (o0 * S0 + o1 * S1));
                        if (even) t0 = fmaf(w, v, t0); else t1 = fmaf(w, v, t1);
                    } else {
                        // ring: w = 1 - sqrt(d2'), pass iff d2' < 1
                        const float w = fmaf(-d2, rsqrtf(d2), 1.0f);
                        if (d2 < 1.0f) {
                            const float v = __ldg(p + (o0 * S0 + o1 * S1));
                            if (even) t0 = fmaf(w, v, t0); else t1 = fmaf(w, v, t1);
                        }
                    }
                }
            }
            accE += t0;
            accO += t1;
        }
    } else {
        // edge LORs (not hit for this dataset): exact per-tap bounds, unscaled
#pragma unroll
        for (int j = 0; j < 4; ++j) {
            const int   kz  = lane + 32 * j;
            const float kzf = (float)kz;
            const float fx = fmaf(kzf, P.y, P.x);
            const float fy = fmaf(kzf, P.w, P.z);
            const int ix = __float2int_rn(fx);
            const int iy = __float2int_rn(fy);
            const float ux = (float)ix - fx;
            const float uy = (float)iy - fy;
            float t0 = 0.0f;
#pragma unroll
            for (int o0 = -2; o0 <= 2; ++o0) {
#pragma unroll
                for (int o1 = -2; o1 <= 2; ++o1) {
                    if (o0 * o0 + o1 * o1 == 8) continue;
                    const int jx = ix + o0;
                    const int jy = iy + o1;
                    const float ddx = ux + (float)o0;
                    const float ddy = uy + (float)o1;
                    const float d2 = ddx * ddx + ddy * ddy;
                    if (d2 < KW2 && (unsigned)jx < (unsigned)G && (unsigned)jy < (unsigned)G) {
                        const float s = d2 * rsqrtf(fmaxf(d2, 1e-30f));
                        const float w = fmaf(-s, IK, 1.0f);
                        t0 = fmaf(w, __ldg(img + jx * S0 + jy * S1 + kz), t0);
                    }
                }
            }
            accE += t0;
        }
    }

    float acc = accE + accO;

    // warp reduction
#pragma unroll
    for (int sft = 16; sft > 0; sft >>= 1)
        acc += __shfl_down_sync(0xFFFFFFFFu, acc, sft);
    if (lane == 0)
        out[lor] = acc * __ldg(&g_stp[set][lor]);
}

// ------------------------ generic fallback -----------------------------------
template <int P0, int P1, int P2>
__global__ __launch_bounds__(128)
void tor_generic_kernel(const float* __restrict__ img_in,
                        const int*   __restrict__ grid,
                        const float* __restrict__ center,
                        const float* __restrict__ size,
                        const float* __restrict__ lors,
                        float*       __restrict__ out,
                        int n_lors)
{
    const int lor = blockIdx.x;
    if (lor >= n_lors) return;
    const int g0 = grid[0], g1 = grid[1], g2 = grid[2];
    const int gs[3]   = { g0, g1, g2 };
    const int istr[3] = { g1 * g2, g2, 1 };
    const int n0 = gs[P0], n1 = gs[P1], n2 = gs[P2];
    const int s0 = istr[P0], s1 = istr[P1], s2 = istr[P2];
    const float* img = img_in;

    const float sz0 = size[P0], sz1 = size[P1], sz2 = size[P2];
    const float vs0 = sz0 / (float)n0, vs1 = sz1 / (float)n1, vs2 = sz2 / (float)n2;
    const float lo0 = center[P0] - sz0 * 0.5f;
    const float lo1 = center[P1] - sz1 * 0.5f;
    const float lo2 = center[P2] - sz2 * 0.5f;

    const float* L = lors + (size_t)lor * 6;
    const float p1x = __ldg(L + 0), p1y = __ldg(L + 1), p1z = __ldg(L + 2);
    const float dx = __ldg(L + 3) - p1x, dy = __ldg(L + 4) - p1y, dz = __ldg(L + 5) - p1z;
    const float len = sqrtf(dx * dx + dy * dy + dz * dz);
    const float step = vs2 * len / fabsf(dz);
    const float inv_dz = 1.0f / dz, inv_vs0 = 1.0f / vs0, inv_vs1 = 1.0f / vs1;
    const float KW2 = 2.8647889756541160f, INV_KW = 0.59081795026046127f;

    float acc = 0.0f;
    for (int kz = threadIdx.x; kz < n2; kz += blockDim.x) {
        const float zc = lo2 + ((float)kz + 0.5f) * vs2;
        const float t  = (zc - p1z) * inv_dz;
        const float fx = (fmaf(t, dx, p1x) - lo0) * inv_vs0 - 0.5f;
        const float fy = (fmaf(t, dy, p1y) - lo1) * inv_vs1 - 0.5f;
        const int ix = __float2int_rn(fx);
        const int iy = __float2int_rn(fy);
#pragma unroll
        for (int o0 = -2; o0 <= 2; ++o0) {
#pragma unroll
            for (int o1 = -2; o1 <= 2; ++o1) {
                if (o0 * o0 + o1 * o1 == 8) continue;
                const int jx = ix + o0, jy = iy + o1;
                const float ddx = (float)jx - fx, ddy = (float)jy - fy;
                const float d2 = ddx * ddx + ddy * ddy;
                if (d2 < KW2 && (unsigned)jx < (unsigned)n0 && (unsigned)jy < (unsigned)n1) {
                    const float s = d2 * rsqrtf(fmaxf(d2, 1e-30f));
                    const float w = fmaf(-s, INV_KW, 1.0f);
                    acc = fmaf(w, __ldg(&img[jx * s0 + jy * s1 + kz * s2]), acc);
                }
            }
        }
    }
#pragma unroll
    for (int sft = 16; sft > 0; sft >>= 1)
        acc += __shfl_down_sync(0xFFFFFFFFu, acc, sft);
    __shared__ float wsum[4];
    if ((threadIdx.x & 31) == 0) wsum[threadIdx.x >> 5] = acc;
    __syncthreads();
    if (threadIdx.x == 0)
        out[lor] = (wsum[0] + wsum[1] + wsum[2] + wsum[3]) * step;
}

extern "C" void kernel_launch(void* const* d_in, const int* in_sizes, int n_in,
                              void* d_out, int out_size)
{
    const float* image  = (const float*)d_in[0];
    const int*   grid   = (const int*)  d_in[1];
    const float* center = (const float*)d_in[2];
    const float* size   = (const float*)d_in[3];
    const float* xlors  = (const float*)d_in[4];
    const float* ylors  = (const float*)d_in[5];
    const float* zlors  = (const float*)d_in[6];
    float* out = (float*)d_out;

    const int nx = in_sizes[4] / 6;
    const int ny = in_sizes[5] / 6;
    const int nz = in_sizes[6] / 6;

    const long long nimg = in_sizes[0];
    const bool fast = (nimg == (long long)G * G * G) &&
                      nx <= MAX_LORS && ny <= MAX_LORS && nz <= MAX_LORS;

    if (fast) {
        const int PT = 256;
        const int W = WARPS_PER_BLOCK;

        // Launch order: ncu capture lands on launch #4 -> hot pz kernel.
        if (nz > 0) prep_kernel<0, 1, 2><<<(nz + PT - 1) / PT, PT>>>(grid, center, size, zlors, nz, 2);
        if (nx > 0) prep_kernel<2, 0, 1><<<(nx + PT - 1) / PT, PT>>>(grid, center, size, xlors, nx, 0);
        if (ny > 0) prep_kernel<1, 0, 2><<<(ny + PT - 1) / PT, PT>>>(grid, center, size, ylors, ny, 1);

        // #4: pz hot kernel (image[jx][jy][kz] -> S0=GSQ, S1=G) — PROFILED
        if (nz > 0) tor_fast_kernel<GSQ, G,   false><<<(nz + W - 1) / W, 32 * W>>>(image, 2, out + nx + ny, nz);

        // #5: transpose for px frame (walked image axis must be stride-1)
        {
            dim3 tb(32, 8), tg(G / 32, G / 32, G);
            transpose_bc_kernel<<<tg, tb>>>(image);
        }

        // #6: px (g_imgT[jy][jx][kz] -> S0=G, S1=GSQ, TPOSE)
        if (nx > 0) tor_fast_kernel<G,   GSQ, true ><<<(nx + W - 1) / W, 32 * W>>>(image, 0, out, nx);
        // #7: py (image[jy][jx][kz] -> S0=G, S1=GSQ)
        if (ny > 0) tor_fast_kernel<G,   GSQ, false><<<(ny + W - 1) / W, 32 * W>>>(image, 1, out + nx, ny);
    } else {
        if (nx > 0) tor_generic_kernel<2, 0, 1><<<nx, 128>>>(image, grid, center, size, xlors, out, nx);
        if (ny > 0) tor_generic_kernel<1, 0, 2><<<ny, 128>>>(image, grid, center, size, ylors, out + nx, ny);
        if (nz > 0) tor_generic_kernel<0, 1, 2><<<nz, 128>>>(image, grid, center, size, zlors, out + nx + ny, nz);
    }
}